// round 2
// baseline (speedup 1.0000x reference)
#include <cuda_runtime.h>

// ---------------------------------------------------------------------------
// MovePredictor: gather(src,tgt embeddings) -> MLP(512->512->256->1)
// Baseline: fp32 SIMT tiled GEMMs, fused gather in GEMM1.
// NOTE: index tensors are int32 (JAX x64 disabled -> int64 request demotes).
// ---------------------------------------------------------------------------

#define N_MOVES_MAX 200000
#define EMB_D       256     // per-node embedding dim
#define K1          512     // 2*D, layer-1 K
#define H1DIM       512     // layer-1 out
#define H2DIM       256     // layer-2 out

// Scratch (allocation-free: __device__ globals)
__device__ float g_H1[(size_t)N_MOVES_MAX * H1DIM];   // ~410 MB
__device__ float g_H2[(size_t)N_MOVES_MAX * H2DIM];   // ~205 MB

#define BM  128
#define BN  128
#define BK  16
#define PAD 4

// C[m,n] = relu( sum_k A[m,k] * W[n,k] + bias[n] )
// GATHER=true: A row m = concat(emb[src[m]], emb[tgt[m]])
template <bool GATHER>
__global__ __launch_bounds__(256, 2)
void gemm_relu_kernel(const float* __restrict__ A,            // [M,K] if !GATHER
                      const float* __restrict__ emb,          // [n_nodes, EMB_D]
                      const int* __restrict__ edge_index,     // [2, n_edges] int32
                      const int* __restrict__ move_idx,       // [M] int32
                      int n_edges,
                      const float* __restrict__ W,            // [N,K] row-major
                      const float* __restrict__ bias,         // [N]
                      float* __restrict__ C,                  // [M,N]
                      int M, int N, int K)
{
    __shared__ float As[BK][BM + PAD];
    __shared__ float Bs[BK][BN + PAD];
    __shared__ int offS[BM];
    __shared__ int offT[BM];

    const int t  = threadIdx.x;
    const int m0 = blockIdx.y * BM;
    const int n0 = blockIdx.x * BN;

    if (GATHER) {
        if (t < BM) {
            int m = m0 + t;
            if (m >= M) m = M - 1;            // clamp; stores are guarded later
            int e = move_idx[m];
            offS[t] = edge_index[e] * EMB_D;
            offT[t] = edge_index[n_edges + e] * EMB_D;
        }
        __syncthreads();
    }

    float acc[8][8];
    #pragma unroll
    for (int i = 0; i < 8; i++)
        #pragma unroll
        for (int j = 0; j < 8; j++) acc[i][j] = 0.f;

    const int tx = t % 16;   // n direction
    const int ty = t / 16;   // m direction

    for (int k0 = 0; k0 < K; k0 += BK) {
        // ---- load A tile: BM x BK = 2048 floats = 512 float4 (2 per thread)
        #pragma unroll
        for (int it = 0; it < 2; it++) {
            int idx = t + it * 256;          // 0..511
            int m   = idx >> 2;              // 0..127
            int kq  = idx & 3;               // float4 slot
            int kk  = k0 + kq * 4;
            float4 v;
            if (GATHER) {
                const float* p = (kk < EMB_D) ? (emb + offS[m] + kk)
                                              : (emb + offT[m] + (kk - EMB_D));
                v = *(const float4*)p;
            } else {
                int gm = m0 + m;
                if (gm >= M) gm = M - 1;
                v = *(const float4*)(A + (size_t)gm * K + kk);
            }
            As[kq * 4 + 0][m] = v.x;
            As[kq * 4 + 1][m] = v.y;
            As[kq * 4 + 2][m] = v.z;
            As[kq * 4 + 3][m] = v.w;
        }
        // ---- load B tile: BN x BK (W is [N,K] row-major)
        #pragma unroll
        for (int it = 0; it < 2; it++) {
            int idx = t + it * 256;
            int n   = idx >> 2;
            int kq  = idx & 3;
            int kk  = k0 + kq * 4;
            float4 v = *(const float4*)(W + (size_t)(n0 + n) * K + kk);
            Bs[kq * 4 + 0][n] = v.x;
            Bs[kq * 4 + 1][n] = v.y;
            Bs[kq * 4 + 2][n] = v.z;
            Bs[kq * 4 + 3][n] = v.w;
        }
        __syncthreads();

        #pragma unroll
        for (int k = 0; k < BK; k++) {
            float a[8], b[8];
            #pragma unroll
            for (int i = 0; i < 8; i++) a[i] = As[k][ty * 8 + i];
            #pragma unroll
            for (int j = 0; j < 8; j++) b[j] = Bs[k][tx * 8 + j];
            #pragma unroll
            for (int i = 0; i < 8; i++)
                #pragma unroll
                for (int j = 0; j < 8; j++)
                    acc[i][j] += a[i] * b[j];
        }
        __syncthreads();
    }

    // ---- epilogue: bias + relu, guarded store
    #pragma unroll
    for (int i = 0; i < 8; i++) {
        int m = m0 + ty * 8 + i;
        if (m < M) {
            #pragma unroll
            for (int j = 0; j < 8; j++) {
                int n = n0 + tx * 8 + j;
                float v = acc[i][j] + bias[n];
                C[(size_t)m * N + n] = v > 0.f ? v : 0.f;
            }
        }
    }
}

// logits[m] = dot(H2[m,:], W3) + b3 ; one warp per move
__global__ void logits_kernel(const float* __restrict__ H2,
                              const float* __restrict__ W3,
                              const float* __restrict__ b3,
                              float* __restrict__ out, int M)
{
    __shared__ float w[H2DIM];
    int t = threadIdx.x;
    if (t < H2DIM) w[t] = W3[t];
    __syncthreads();

    int warp = t >> 5;
    int lane = t & 31;
    int m = blockIdx.x * 8 + warp;
    if (m >= M) return;

    const float* h = H2 + (size_t)m * H2DIM;
    float s = 0.f;
    #pragma unroll
    for (int j = 0; j < 8; j++)
        s += h[lane + 32 * j] * w[lane + 32 * j];
    #pragma unroll
    for (int o = 16; o > 0; o >>= 1)
        s += __shfl_xor_sync(0xffffffffu, s, o);
    if (lane == 0) out[m] = s + b3[0];
}

extern "C" void kernel_launch(void* const* d_in, const int* in_sizes, int n_in,
                              void* d_out, int out_size)
{
    const float* emb        = (const float*)d_in[0];
    const int*   edge_index = (const int*)d_in[1];
    const int*   move_idx   = (const int*)d_in[2];
    const float* W1 = (const float*)d_in[3];
    const float* b1 = (const float*)d_in[4];
    const float* W2 = (const float*)d_in[5];
    const float* b2 = (const float*)d_in[6];
    const float* W3 = (const float*)d_in[7];
    const float* b3 = (const float*)d_in[8];
    float* out = (float*)d_out;

    int M = in_sizes[2];                 // number of moves
    int n_edges = in_sizes[1] / 2;

    void *h1p = nullptr, *h2p = nullptr;
    cudaGetSymbolAddress(&h1p, g_H1);
    cudaGetSymbolAddress(&h2p, g_H2);
    float* H1 = (float*)h1p;
    float* H2 = (float*)h2p;

    int mtiles = (M + BM - 1) / BM;

    // Layer 1: gather + [M,512] @ W1^T -> relu -> H1 [M,512]
    {
        dim3 grid(H1DIM / BN, mtiles);
        gemm_relu_kernel<true><<<grid, 256>>>(
            nullptr, emb, edge_index, move_idx, n_edges,
            W1, b1, H1, M, H1DIM, K1);
    }
    // Layer 2: H1 @ W2^T -> relu -> H2 [M,256]
    {
        dim3 grid(H2DIM / BN, mtiles);
        gemm_relu_kernel<false><<<grid, 256>>>(
            H1, nullptr, nullptr, nullptr, 0,
            W2, b2, H2, M, H2DIM, H1DIM);
    }
    // Layer 3: logits
    {
        int grid = (M + 7) / 8;
        logits_kernel<<<grid, 256>>>(H2, W3, b3, out, M);
    }
}

// round 4
// speedup vs baseline: 3.2719x; 3.2719x over previous
#include <cuda_runtime.h>
#include <cuda_bf16.h>
#include <cstdint>

// ---------------------------------------------------------------------------
// MovePredictor via mma.sync (portable HMMA, no sm_103a-only features):
// gather -> MLP(512->512->256->1), split-bf16 (3 passes) for fp32 accuracy.
// ---------------------------------------------------------------------------

#define N_MOVES_MAX 200000
#define EMB_D   256
#define K1      512
#define H1DIM   512
#define H2DIM   256
#define NTHREADS 256

#define BM 128
#define BN 128
#define BK 32            // bf16 elems per k-chunk
#define RSTRIDE 80       // smem row stride bytes (32 bf16 = 64B + 16B pad)

// smem offsets (bytes)
#define SA_H 0
#define SA_L 10240
#define SB_H 20480
#define SB_L 30720
#define AUX  40960       // layer1: offS(512) offT(512) b1s(512); layer2: b2s(1024) w3s(1024)

// scratch globals (allocation-free)
__device__ __nv_bfloat16 g_H1h[(size_t)N_MOVES_MAX * H1DIM];
__device__ __nv_bfloat16 g_H1l[(size_t)N_MOVES_MAX * H1DIM];
__device__ __nv_bfloat16 g_W1h[(size_t)H1DIM * K1];
__device__ __nv_bfloat16 g_W1l[(size_t)H1DIM * K1];
__device__ __nv_bfloat16 g_W2h[(size_t)H2DIM * H1DIM];
__device__ __nv_bfloat16 g_W2l[(size_t)H2DIM * H1DIM];

// ---------------- helpers ----------------
__device__ __forceinline__ uint32_t smem_u32(const void* p) {
    uint32_t a;
    asm("{ .reg .u64 t; cvta.to.shared.u64 t, %1; cvt.u32.u64 %0, t; }"
        : "=r"(a) : "l"(p));
    return a;
}
__device__ __forceinline__ void cp16(uint32_t dst, const void* src) {
    asm volatile("cp.async.cg.shared.global [%0], [%1], 16;" :: "r"(dst), "l"(src));
}
__device__ __forceinline__ void cp_wait_all() {
    asm volatile("cp.async.commit_group;\n\tcp.async.wait_group 0;" ::: "memory");
}
__device__ __forceinline__ void ldsm_x4(uint32_t* r, uint32_t addr) {
    asm volatile("ldmatrix.sync.aligned.m8n8.x4.shared.b16 {%0,%1,%2,%3}, [%4];"
                 : "=r"(r[0]), "=r"(r[1]), "=r"(r[2]), "=r"(r[3]) : "r"(addr));
}
__device__ __forceinline__ void mma_bf16(float* c, const uint32_t* a,
                                         uint32_t b0, uint32_t b1) {
    asm volatile(
        "mma.sync.aligned.m16n8k16.row.col.f32.bf16.bf16.f32 "
        "{%0,%1,%2,%3}, {%4,%5,%6,%7}, {%8,%9}, {%0,%1,%2,%3};"
        : "+f"(c[0]), "+f"(c[1]), "+f"(c[2]), "+f"(c[3])
        : "r"(a[0]), "r"(a[1]), "r"(a[2]), "r"(a[3]), "r"(b0), "r"(b1));
}
__device__ __forceinline__ uint32_t pack_bf2(__nv_bfloat16 a, __nv_bfloat16 b) {
    __nv_bfloat162 v(a, b);
    return *reinterpret_cast<uint32_t*>(&v);
}
__device__ __forceinline__ void split2(float x0, float x1, uint32_t& hi, uint32_t& lo) {
    __nv_bfloat16 h0 = __float2bfloat16_rn(x0);
    __nv_bfloat16 h1 = __float2bfloat16_rn(x1);
    __nv_bfloat16 l0 = __float2bfloat16_rn(x0 - __bfloat162float(h0));
    __nv_bfloat16 l1 = __float2bfloat16_rn(x1 - __bfloat162float(h1));
    hi = pack_bf2(h0, h1);
    lo = pack_bf2(l0, l1);
}

// ---------------- weight prep + output init ----------------
__global__ void prep_weights(const float* __restrict__ W1, const float* __restrict__ W2)
{
    int i = blockIdx.x * blockDim.x + threadIdx.x;
    int n1 = H1DIM * K1;
    int n2 = H2DIM * H1DIM;
    if (i < n1) {
        float x = W1[i];
        __nv_bfloat16 h = __float2bfloat16_rn(x);
        g_W1h[i] = h;
        g_W1l[i] = __float2bfloat16_rn(x - __bfloat162float(h));
    } else if (i < n1 + n2) {
        int j = i - n1;
        float x = W2[j];
        __nv_bfloat16 h = __float2bfloat16_rn(x);
        g_W2h[j] = h;
        g_W2l[j] = __float2bfloat16_rn(x - __bfloat162float(h));
    }
}
__global__ void init_out(float* __restrict__ out, const float* __restrict__ b3, int M)
{
    int i = blockIdx.x * blockDim.x + threadIdx.x;
    if (i < M) out[i] = b3[0];
}

// ---------------- layer 1: gather + GEMM(K=512,N=512) + relu -> split H1 ----------------
__global__ __launch_bounds__(NTHREADS, 2)
void mm_layer1(const float* __restrict__ emb,
               const int* __restrict__ edge_index,
               const int* __restrict__ move_idx, int n_edges,
               const float* __restrict__ b1, int M)
{
    __shared__ char sm[AUX + 1536];
    const uint32_t sbase = smem_u32(sm);
    const int t = threadIdx.x;
    const int lane = t & 31;
    const int w = t >> 5;
    const int warp_m = w & 3;        // 4 warps in M
    const int warp_n = w >> 2;       // 2 warps in N
    const int m0 = blockIdx.y * BM;
    const int n0 = blockIdx.x * BN;

    int* offS = (int*)(sm + AUX);
    int* offT = (int*)(sm + AUX + 512);
    float* b1s = (float*)(sm + AUX + 1024);
    if (t < BM) {
        int m = m0 + t;
        if (m >= M) m = M - 1;
        int e = move_idx[m];
        offS[t] = edge_index[e] * EMB_D;
        offT[t] = edge_index[n_edges + e] * EMB_D;
        b1s[t]  = b1[n0 + t];
    }
    __syncthreads();

    // per-thread ldmatrix base addresses
    const uint32_t aA = sbase + SA_H + (warp_m * 32 + (lane & 15)) * RSTRIDE + (lane >> 4) * 16;
    const uint32_t aB = sbase + SB_H + (warp_n * 64 + (lane & 15)) * RSTRIDE + (lane >> 4) * 16;

    float acc[2][8][4];
    #pragma unroll
    for (int i = 0; i < 2; i++)
        #pragma unroll
        for (int j = 0; j < 8; j++)
            #pragma unroll
            for (int k = 0; k < 4; k++) acc[i][j][k] = 0.f;

    for (int it = 0; it < K1 / BK; it++) {
        const int k0 = it * BK;
        // B: cp.async pre-split W1 (hi & lo), 128 rows x 64B each
        #pragma unroll
        for (int i = 0; i < 4; i++) {
            int g = t + i * NTHREADS;          // 1024
            int buf = g >> 9;                  // 0:hi 1:lo
            int rem = g & 511;
            int n = rem >> 2, ch = rem & 3;
            const __nv_bfloat16* src = (buf ? g_W1l : g_W1h) +
                                       (size_t)(n0 + n) * K1 + k0 + ch * 8;
            cp16(sbase + (buf ? SB_L : SB_H) + n * RSTRIDE + ch * 16, src);
        }
        // A: gather fp32, split, STS
        #pragma unroll
        for (int i = 0; i < 4; i++) {
            int g = t + i * NTHREADS;          // 1024 float4 granules
            int m = g >> 3, cq = g & 7;
            int kk = k0 + cq * 4;
            const float* p = (kk < EMB_D) ? (emb + offS[m] + kk)
                                          : (emb + offT[m] + (kk - EMB_D));
            float4 v = *(const float4*)p;
            uint32_t h01, l01, h23, l23;
            split2(v.x, v.y, h01, l01);
            split2(v.z, v.w, h23, l23);
            uint2 hv{h01, h23}, lv{l01, l23};
            *(uint2*)(sm + SA_H + m * RSTRIDE + cq * 8) = hv;
            *(uint2*)(sm + SA_L + m * RSTRIDE + cq * 8) = lv;
        }
        cp_wait_all();
        __syncthreads();

        #pragma unroll
        for (int kt = 0; kt < 2; kt++) {
            uint32_t aH[2][4], aL[2][4];
            #pragma unroll
            for (int mt = 0; mt < 2; mt++) {
                ldsm_x4(aH[mt], aA + mt * 16 * RSTRIDE + kt * 32);
                ldsm_x4(aL[mt], aA + 10240 + mt * 16 * RSTRIDE + kt * 32);
            }
            #pragma unroll
            for (int nb = 0; nb < 4; nb++) {
                uint32_t bh[4], bl[4];
                ldsm_x4(bh, aB + nb * 16 * RSTRIDE + kt * 32);
                ldsm_x4(bl, aB + 10240 + nb * 16 * RSTRIDE + kt * 32);
                #pragma unroll
                for (int mt = 0; mt < 2; mt++) {
                    mma_bf16(acc[mt][2 * nb],     aH[mt], bh[0], bh[2]);
                    mma_bf16(acc[mt][2 * nb],     aH[mt], bl[0], bl[2]);
                    mma_bf16(acc[mt][2 * nb],     aL[mt], bh[0], bh[2]);
                    mma_bf16(acc[mt][2 * nb + 1], aH[mt], bh[1], bh[3]);
                    mma_bf16(acc[mt][2 * nb + 1], aH[mt], bl[1], bl[3]);
                    mma_bf16(acc[mt][2 * nb + 1], aL[mt], bh[1], bh[3]);
                }
            }
        }
        __syncthreads();
    }

    // epilogue: bias + relu, split-store H1
    #pragma unroll
    for (int mt = 0; mt < 2; mt++) {
        #pragma unroll
        for (int h = 0; h < 2; h++) {
            int r = m0 + warp_m * 32 + mt * 16 + (lane >> 2) + 8 * h;
            if (r < M) {
                #pragma unroll
                for (int nt = 0; nt < 8; nt++) {
                    int cl = warp_n * 64 + nt * 8 + (lane & 3) * 2;
                    float v0 = acc[mt][nt][2 * h + 0] + b1s[cl];
                    float v1 = acc[mt][nt][2 * h + 1] + b1s[cl + 1];
                    v0 = v0 > 0.f ? v0 : 0.f;
                    v1 = v1 > 0.f ? v1 : 0.f;
                    uint32_t hi, lo;
                    split2(v0, v1, hi, lo);
                    size_t o = (size_t)r * H1DIM + n0 + cl;
                    *(uint32_t*)(g_H1h + o) = hi;
                    *(uint32_t*)(g_H1l + o) = lo;
                }
            }
        }
    }
}

// ---------------- layer 2 + 3: GEMM(K=512,N=256) + relu + dot(W3) -> atomic logits ----------------
__global__ __launch_bounds__(NTHREADS, 2)
void mm_layer2(const float* __restrict__ b2,
               const float* __restrict__ W3,
               float* __restrict__ out, int M)
{
    __shared__ char sm[AUX + 2048];
    const uint32_t sbase = smem_u32(sm);
    const int t = threadIdx.x;
    const int lane = t & 31;
    const int w = t >> 5;
    const int warp_m = w & 3;
    const int warp_n = w >> 2;
    const int m0 = blockIdx.y * BM;
    const int n0 = blockIdx.x * BN;   // 0 or 128

    float* b2s = (float*)(sm + AUX);          // 256 floats (global col index)
    float* w3s = (float*)(sm + AUX + 1024);
    b2s[t] = b2[t];
    w3s[t] = W3[t];
    __syncthreads();

    const uint32_t aA = sbase + SA_H + (warp_m * 32 + (lane & 15)) * RSTRIDE + (lane >> 4) * 16;
    const uint32_t aB = sbase + SB_H + (warp_n * 64 + (lane & 15)) * RSTRIDE + (lane >> 4) * 16;

    float acc[2][8][4];
    #pragma unroll
    for (int i = 0; i < 2; i++)
        #pragma unroll
        for (int j = 0; j < 8; j++)
            #pragma unroll
            for (int k = 0; k < 4; k++) acc[i][j][k] = 0.f;

    for (int it = 0; it < H1DIM / BK; it++) {
        const int k0 = it * BK;
        // A: pre-split H1
        #pragma unroll
        for (int i = 0; i < 4; i++) {
            int g = t + i * NTHREADS;
            int buf = g >> 9;
            int rem = g & 511;
            int m = rem >> 2, ch = rem & 3;
            int gm = m0 + m; if (gm >= M) gm = M - 1;
            const __nv_bfloat16* src = (buf ? g_H1l : g_H1h) +
                                       (size_t)gm * H1DIM + k0 + ch * 8;
            cp16(sbase + (buf ? SA_L : SA_H) + m * RSTRIDE + ch * 16, src);
        }
        // B: pre-split W2
        #pragma unroll
        for (int i = 0; i < 4; i++) {
            int g = t + i * NTHREADS;
            int buf = g >> 9;
            int rem = g & 511;
            int n = rem >> 2, ch = rem & 3;
            const __nv_bfloat16* src = (buf ? g_W2l : g_W2h) +
                                       (size_t)(n0 + n) * H1DIM + k0 + ch * 8;
            cp16(sbase + (buf ? SB_L : SB_H) + n * RSTRIDE + ch * 16, src);
        }
        cp_wait_all();
        __syncthreads();

        #pragma unroll
        for (int kt = 0; kt < 2; kt++) {
            uint32_t aH[2][4], aL[2][4];
            #pragma unroll
            for (int mt = 0; mt < 2; mt++) {
                ldsm_x4(aH[mt], aA + mt * 16 * RSTRIDE + kt * 32);
                ldsm_x4(aL[mt], aA + 10240 + mt * 16 * RSTRIDE + kt * 32);
            }
            #pragma unroll
            for (int nb = 0; nb < 4; nb++) {
                uint32_t bh[4], bl[4];
                ldsm_x4(bh, aB + nb * 16 * RSTRIDE + kt * 32);
                ldsm_x4(bl, aB + 10240 + nb * 16 * RSTRIDE + kt * 32);
                #pragma unroll
                for (int mt = 0; mt < 2; mt++) {
                    mma_bf16(acc[mt][2 * nb],     aH[mt], bh[0], bh[2]);
                    mma_bf16(acc[mt][2 * nb],     aH[mt], bl[0], bl[2]);
                    mma_bf16(acc[mt][2 * nb],     aL[mt], bh[0], bh[2]);
                    mma_bf16(acc[mt][2 * nb + 1], aH[mt], bh[1], bh[3]);
                    mma_bf16(acc[mt][2 * nb + 1], aH[mt], bl[1], bl[3]);
                    mma_bf16(acc[mt][2 * nb + 1], aL[mt], bh[1], bh[3]);
                }
            }
        }
        __syncthreads();
    }

    // epilogue: bias + relu + partial dot(W3), quad-reduce, atomicAdd
    #pragma unroll
    for (int mt = 0; mt < 2; mt++) {
        #pragma unroll
        for (int h = 0; h < 2; h++) {
            int r = m0 + warp_m * 32 + mt * 16 + (lane >> 2) + 8 * h;
            float p = 0.f;
            #pragma unroll
            for (int nt = 0; nt < 8; nt++) {
                int c = n0 + warp_n * 64 + nt * 8 + (lane & 3) * 2;
                float v0 = acc[mt][nt][2 * h + 0] + b2s[c];
                float v1 = acc[mt][nt][2 * h + 1] + b2s[c + 1];
                v0 = v0 > 0.f ? v0 : 0.f;
                v1 = v1 > 0.f ? v1 : 0.f;
                p += v0 * w3s[c] + v1 * w3s[c + 1];
            }
            p += __shfl_xor_sync(0xffffffffu, p, 1);
            p += __shfl_xor_sync(0xffffffffu, p, 2);
            if ((lane & 3) == 0 && r < M) atomicAdd(out + r, p);
        }
    }
}

// ---------------- launch ----------------
extern "C" void kernel_launch(void* const* d_in, const int* in_sizes, int n_in,
                              void* d_out, int out_size)
{
    const float* emb        = (const float*)d_in[0];
    const int*   edge_index = (const int*)d_in[1];
    const int*   move_idx   = (const int*)d_in[2];
    const float* W1 = (const float*)d_in[3];
    const float* b1 = (const float*)d_in[4];
    const float* W2 = (const float*)d_in[5];
    const float* b2 = (const float*)d_in[6];
    const float* W3 = (const float*)d_in[7];
    const float* b3 = (const float*)d_in[8];
    float* out = (float*)d_out;

    int M = in_sizes[2];
    int n_edges = in_sizes[1] / 2;
    int mtiles = (M + BM - 1) / BM;

    {   // weight split + output init (out = b3)
        int total = H1DIM * K1 + H2DIM * H1DIM;
        prep_weights<<<(total + 1023) / 1024, 1024>>>(W1, W2);
        init_out<<<(M + 255) / 256, 256>>>(out, b3, M);
    }
    {   // layer 1
        dim3 grid(H1DIM / BN, mtiles);
        mm_layer1<<<grid, NTHREADS>>>(emb, edge_index, move_idx, n_edges, b1, M);
    }
    {   // layer 2 + 3 (atomic partial logits)
        dim3 grid(H2DIM / BN, mtiles);
        mm_layer2<<<grid, NTHREADS>>>(b2, W3, out, M);
    }
}

// round 5
// speedup vs baseline: 4.8443x; 1.4806x over previous
#include <cuda_runtime.h>
#include <cuda_bf16.h>
#include <cstdint>

// ---------------------------------------------------------------------------
// MovePredictor: logits = W3 . relu(W2 . relu(W1.[e_src;e_tgt] + b1) + b2) + b3
// Trick: PQ = emb @ [W1_left; W1_right]^T over NODES (half the layer-1 FLOPs),
// then h1[m] = relu(PQ[src,0:512] + PQ[tgt,512:1024] + b1) built in-kernel.
// Split-bf16 (hi+lo, 3 MMA passes) mma.sync GEMMs, 64x64 warp tiles,
// double-buffered cp.async.
// ---------------------------------------------------------------------------

#define N_NODES_MAX 100000
#define EMB_D   256
#define H1DIM   512
#define H2DIM   256
#define PQN     1024            // stacked P(512) + Q(512)

#define BM 128
#define BN 256
#define BK 32
#define RS 80                   // smem row stride bytes (64B data + 16B pad)

// stage layout (bytes within one stage)
#define A_H 0
#define A_L 10240
#define B_H 20480
#define B_L 40960
#define STG 61440
#define AUXO 122880             // aux after 2 stages
#define SMEM_TOTAL (AUXO + 6144)

// ---- device globals (allocation-free scratch) ----
__device__ float        g_PQ[(size_t)N_NODES_MAX * PQN];       // 409.6 MB
__device__ __nv_bfloat16 g_Eh[(size_t)N_NODES_MAX * EMB_D];
__device__ __nv_bfloat16 g_El[(size_t)N_NODES_MAX * EMB_D];
__device__ __nv_bfloat16 g_W1sh[(size_t)PQN * EMB_D];          // stacked W1
__device__ __nv_bfloat16 g_W1sl[(size_t)PQN * EMB_D];
__device__ __nv_bfloat16 g_W2h[(size_t)H2DIM * H1DIM];
__device__ __nv_bfloat16 g_W2l[(size_t)H2DIM * H1DIM];

// ---------------- helpers ----------------
__device__ __forceinline__ uint32_t smem_u32(const void* p) {
    uint32_t a;
    asm("{ .reg .u64 t; cvta.to.shared.u64 t, %1; cvt.u32.u64 %0, t; }"
        : "=r"(a) : "l"(p));
    return a;
}
__device__ __forceinline__ void cp16(uint32_t dst, const void* src) {
    asm volatile("cp.async.cg.shared.global [%0], [%1], 16;" :: "r"(dst), "l"(src));
}
__device__ __forceinline__ void cp_commit() {
    asm volatile("cp.async.commit_group;" ::: "memory");
}
__device__ __forceinline__ void cp_wait0() {
    asm volatile("cp.async.wait_group 0;" ::: "memory");
}
__device__ __forceinline__ void ldsm_x4(uint32_t* r, uint32_t addr) {
    asm volatile("ldmatrix.sync.aligned.m8n8.x4.shared.b16 {%0,%1,%2,%3}, [%4];"
                 : "=r"(r[0]), "=r"(r[1]), "=r"(r[2]), "=r"(r[3]) : "r"(addr));
}
__device__ __forceinline__ void mma_bf16(float* c, const uint32_t* a,
                                         uint32_t b0, uint32_t b1) {
    asm volatile(
        "mma.sync.aligned.m16n8k16.row.col.f32.bf16.bf16.f32 "
        "{%0,%1,%2,%3}, {%4,%5,%6,%7}, {%8,%9}, {%0,%1,%2,%3};"
        : "+f"(c[0]), "+f"(c[1]), "+f"(c[2]), "+f"(c[3])
        : "r"(a[0]), "r"(a[1]), "r"(a[2]), "r"(a[3]), "r"(b0), "r"(b1));
}
__device__ __forceinline__ uint32_t pack_bf2(__nv_bfloat16 a, __nv_bfloat16 b) {
    __nv_bfloat162 v(a, b);
    return *reinterpret_cast<uint32_t*>(&v);
}
__device__ __forceinline__ void split2(float x0, float x1, uint32_t& hi, uint32_t& lo) {
    __nv_bfloat16 h0 = __float2bfloat16_rn(x0);
    __nv_bfloat16 h1 = __float2bfloat16_rn(x1);
    __nv_bfloat16 l0 = __float2bfloat16_rn(x0 - __bfloat162float(h0));
    __nv_bfloat16 l1 = __float2bfloat16_rn(x1 - __bfloat162float(h1));
    hi = pack_bf2(h0, h1);
    lo = pack_bf2(l0, l1);
}

// shared 64x64-warp MMA block: 2 k16 steps over one 32-k chunk, 3 passes
__device__ __forceinline__ void mma_chunk(uint32_t stg, int lane, int warp_m,
                                          int warp_n, float acc[4][8][4]) {
    const uint32_t aB = stg + A_H + (warp_m * 64 + (lane & 15)) * RS + (lane >> 4) * 16;
    const uint32_t bB = stg + B_H + (warp_n * 64 + (lane & 15)) * RS + (lane >> 4) * 16;
    #pragma unroll
    for (int kt = 0; kt < 2; kt++) {
        uint32_t aH[4][4], aL[4][4], bH[4][4], bL[4][4];
        #pragma unroll
        for (int mt = 0; mt < 4; mt++) {
            ldsm_x4(aH[mt], aB + mt * 16 * RS + kt * 32);
            ldsm_x4(aL[mt], aB + (A_L - A_H) + mt * 16 * RS + kt * 32);
        }
        #pragma unroll
        for (int nb = 0; nb < 4; nb++) {
            ldsm_x4(bH[nb], bB + nb * 16 * RS + kt * 32);
            ldsm_x4(bL[nb], bB + (B_L - B_H) + nb * 16 * RS + kt * 32);
        }
        #pragma unroll
        for (int mt = 0; mt < 4; mt++)
            #pragma unroll
            for (int nb = 0; nb < 4; nb++) {
                mma_bf16(acc[mt][2 * nb],     aH[mt], bH[nb][0], bH[nb][2]);
                mma_bf16(acc[mt][2 * nb],     aH[mt], bL[nb][0], bL[nb][2]);
                mma_bf16(acc[mt][2 * nb],     aL[mt], bH[nb][0], bH[nb][2]);
                mma_bf16(acc[mt][2 * nb + 1], aH[mt], bH[nb][1], bH[nb][3]);
                mma_bf16(acc[mt][2 * nb + 1], aH[mt], bL[nb][1], bL[nb][3]);
                mma_bf16(acc[mt][2 * nb + 1], aL[mt], bH[nb][1], bH[nb][3]);
            }
    }
}

// ---------------- prep: split emb, stacked W1, W2 ----------------
__global__ void prep_split(const float* __restrict__ emb, int n_emb,
                           const float* __restrict__ W1,
                           const float* __restrict__ W2)
{
    int total = n_emb + PQN * EMB_D + H2DIM * H1DIM;
    for (int i = blockIdx.x * blockDim.x + threadIdx.x; i < total;
         i += gridDim.x * blockDim.x) {
        if (i < n_emb) {
            float x = emb[i];
            __nv_bfloat16 h = __float2bfloat16_rn(x);
            g_Eh[i] = h;
            g_El[i] = __float2bfloat16_rn(x - __bfloat162float(h));
        } else if (i < n_emb + PQN * EMB_D) {
            int j = i - n_emb;
            int r = j >> 8, k = j & 255;
            float x = W1[(size_t)(r & 511) * 512 + k + ((r >> 9) << 8)];
            __nv_bfloat16 h = __float2bfloat16_rn(x);
            g_W1sh[j] = h;
            g_W1sl[j] = __float2bfloat16_rn(x - __bfloat162float(h));
        } else {
            int j = i - n_emb - PQN * EMB_D;
            float x = W2[j];
            __nv_bfloat16 h = __float2bfloat16_rn(x);
            g_W2h[j] = h;
            g_W2l[j] = __float2bfloat16_rn(x - __bfloat162float(h));
        }
    }
}
__global__ void init_out(float* __restrict__ out, const float* __restrict__ b3, int M)
{
    int i = blockIdx.x * blockDim.x + threadIdx.x;
    if (i < M) out[i] = b3[0];
}

// ---------------- GEMM 1: PQ = emb @ W1s^T  (M=n_nodes, N=1024, K=256) ----------------
__global__ __launch_bounds__(256, 1)
void gemm_pq(int n_nodes)
{
    extern __shared__ char sm[];
    const uint32_t sb = smem_u32(sm);
    const int t = threadIdx.x, lane = t & 31, w = t >> 5;
    const int warp_m = w >> 2, warp_n = w & 3;
    const int m0 = blockIdx.y * BM;
    const int n0 = blockIdx.x * BN;

    float acc[4][8][4];
    #pragma unroll
    for (int a = 0; a < 4; a++)
        #pragma unroll
        for (int b = 0; b < 8; b++)
            #pragma unroll
            for (int c = 0; c < 4; c++) acc[a][b][c] = 0.f;

    auto issue = [&](uint32_t stg, int ch) {
        int k0 = ch * BK;
        #pragma unroll
        for (int i = 0; i < 4; i++) {           // A: 1024 cp16
            int g = t + i * 256;
            int buf = g >> 9, rem = g & 511;
            int row = rem >> 2, c = rem & 3;
            int gm = m0 + row; if (gm >= n_nodes) gm = n_nodes - 1;
            const __nv_bfloat16* src = (buf ? g_El : g_Eh) + (size_t)gm * EMB_D + k0 + c * 8;
            cp16(sb + stg + (buf ? A_L : A_H) + row * RS + c * 16, src);
        }
        #pragma unroll
        for (int i = 0; i < 8; i++) {           // B: 2048 cp16
            int g = t + i * 256;
            int buf = g >> 10, rem = g & 1023;
            int row = rem >> 2, c = rem & 3;
            const __nv_bfloat16* src = (buf ? g_W1sl : g_W1sh) +
                                       (size_t)(n0 + row) * EMB_D + k0 + c * 8;
            cp16(sb + stg + (buf ? B_L : B_H) + row * RS + c * 16, src);
        }
        cp_commit();
    };

    issue(0, 0);
    const int CH = EMB_D / BK;       // 8
    for (int ch = 0; ch < CH; ch++) {
        cp_wait0();
        __syncthreads();
        if (ch + 1 < CH) issue(((ch + 1) & 1) * STG, ch + 1);
        mma_chunk((ch & 1) * STG + sb, lane, warp_m, warp_n, acc);
    }

    // store fp32 PQ
    #pragma unroll
    for (int mt = 0; mt < 4; mt++)
        #pragma unroll
        for (int h = 0; h < 2; h++) {
            int r = m0 + warp_m * 64 + mt * 16 + (lane >> 2) + 8 * h;
            if (r < n_nodes) {
                #pragma unroll
                for (int nb = 0; nb < 8; nb++) {
                    int c = n0 + warp_n * 64 + nb * 8 + (lane & 3) * 2;
                    float2 v{acc[mt][nb][2 * h], acc[mt][nb][2 * h + 1]};
                    *(float2*)(g_PQ + (size_t)r * PQN + c) = v;
                }
            }
        }
}

// ---------------- GEMM 2+3: h1 on-the-fly, GEMM vs W2, relu, dot W3 ----------------
__global__ __launch_bounds__(256, 1)
void gemm_l23(const int* __restrict__ edge_index,
              const int* __restrict__ move_idx, int n_edges,
              const float* __restrict__ b1, const float* __restrict__ b2,
              const float* __restrict__ W3, float* __restrict__ out, int M)
{
    extern __shared__ char sm[];
    const uint32_t sb = smem_u32(sm);
    const int t = threadIdx.x, lane = t & 31, w = t >> 5;
    const int warp_m = w >> 2, warp_n = w & 3;
    const int m0 = blockIdx.x * BM;

    int*   offS = (int*)(sm + AUXO);
    int*   offT = (int*)(sm + AUXO + 512);
    float* b1s  = (float*)(sm + AUXO + 1024);     // 512 floats
    float* b2s  = (float*)(sm + AUXO + 3072);     // 256 floats
    float* w3s  = (float*)(sm + AUXO + 4096);     // 256 floats

    if (t < 128) {
        int m = m0 + t; if (m >= M) m = M - 1;
        int e = move_idx[m];
        offS[t] = edge_index[e] * PQN;
        offT[t] = edge_index[n_edges + e] * PQN + 512;
    }
    b1s[t]       = b1[t];
    b1s[t + 256] = b1[t + 256];
    if (t < 256) { b2s[t] = b2[t]; w3s[t] = W3[t]; }
    __syncthreads();

    float acc[4][8][4];
    #pragma unroll
    for (int a = 0; a < 4; a++)
        #pragma unroll
        for (int b = 0; b < 8; b++)
            #pragma unroll
            for (int c = 0; c < 4; c++) acc[a][b][c] = 0.f;

    const int r  = t >> 1;          // A row handled by this thread
    const int hh = t & 1;           // 16-col half

    auto issueB = [&](uint32_t stg, int ch) {
        int k0 = ch * BK;
        #pragma unroll
        for (int i = 0; i < 8; i++) {
            int g = t + i * 256;
            int buf = g >> 10, rem = g & 1023;
            int row = rem >> 2, c = rem & 3;
            const __nv_bfloat16* src = (buf ? g_W2l : g_W2h) +
                                       (size_t)row * H1DIM + k0 + c * 8;
            cp16(sb + stg + (buf ? B_L : B_H) + row * RS + c * 16, src);
        }
        cp_commit();
    };
    auto ldgA = [&](int ch, float4* S, float4* T) {
        int cb = ch * BK + hh * 16;
        const float* ps = g_PQ + offS[r] + cb;
        const float* pt = g_PQ + offT[r] + cb;
        #pragma unroll
        for (int q = 0; q < 4; q++) {
            S[q] = *(const float4*)(ps + q * 4);
            T[q] = *(const float4*)(pt + q * 4);
        }
    };
    auto stsA = [&](uint32_t stg, int ch, const float4* S, const float4* T) {
        int cb = ch * BK + hh * 16;
        #pragma unroll
        for (int q = 0; q < 4; q++) {
            int c = cb + q * 4;
            float u0 = S[q].x + T[q].x + b1s[c];
            float u1 = S[q].y + T[q].y + b1s[c + 1];
            float u2 = S[q].z + T[q].z + b1s[c + 2];
            float u3 = S[q].w + T[q].w + b1s[c + 3];
            u0 = u0 > 0.f ? u0 : 0.f;  u1 = u1 > 0.f ? u1 : 0.f;
            u2 = u2 > 0.f ? u2 : 0.f;  u3 = u3 > 0.f ? u3 : 0.f;
            uint32_t h01, l01, h23, l23;
            split2(u0, u1, h01, l01);
            split2(u2, u3, h23, l23);
            int o = r * RS + hh * 32 + q * 8;
            *(uint2*)(sm + stg + A_H + o) = uint2{h01, h23};
            *(uint2*)(sm + stg + A_L + o) = uint2{l01, l23};
        }
    };

    // prologue: stage 0
    {
        issueB(0, 0);
        float4 S[4], T[4];
        ldgA(0, S, T);
        stsA(0, 0, S, T);
    }
    const int CH = H1DIM / BK;      // 16
    for (int ch = 0; ch < CH; ch++) {
        cp_wait0();
        __syncthreads();
        float4 S[4], T[4];
        if (ch + 1 < CH) {
            issueB(((ch + 1) & 1) * STG, ch + 1);
            ldgA(ch + 1, S, T);
        }
        mma_chunk((ch & 1) * STG + sb, lane, warp_m, warp_n, acc);
        if (ch + 1 < CH) stsA(((ch + 1) & 1) * STG, ch + 1, S, T);
    }

    // epilogue: +b2, relu, dot w3, quad-reduce, atomic add
    #pragma unroll
    for (int mt = 0; mt < 4; mt++)
        #pragma unroll
        for (int h = 0; h < 2; h++) {
            int rr = m0 + warp_m * 64 + mt * 16 + (lane >> 2) + 8 * h;
            float p = 0.f;
            #pragma unroll
            for (int nb = 0; nb < 8; nb++) {
                int c = warp_n * 64 + nb * 8 + (lane & 3) * 2;
                float v0 = acc[mt][nb][2 * h]     + b2s[c];
                float v1 = acc[mt][nb][2 * h + 1] + b2s[c + 1];
                v0 = v0 > 0.f ? v0 : 0.f;
                v1 = v1 > 0.f ? v1 : 0.f;
                p += v0 * w3s[c] + v1 * w3s[c + 1];
            }
            p += __shfl_xor_sync(0xffffffffu, p, 1);
            p += __shfl_xor_sync(0xffffffffu, p, 2);
            if ((lane & 3) == 0 && rr < M) atomicAdd(out + rr, p);
        }
}

// ---------------- launch ----------------
extern "C" void kernel_launch(void* const* d_in, const int* in_sizes, int n_in,
                              void* d_out, int out_size)
{
    const float* emb        = (const float*)d_in[0];
    const int*   edge_index = (const int*)d_in[1];
    const int*   move_idx   = (const int*)d_in[2];
    const float* W1 = (const float*)d_in[3];
    const float* b1 = (const float*)d_in[4];
    const float* W2 = (const float*)d_in[5];
    const float* b2 = (const float*)d_in[6];
    const float* W3 = (const float*)d_in[7];
    const float* b3 = (const float*)d_in[8];
    float* out = (float*)d_out;

    int n_emb   = in_sizes[0];
    int n_nodes = n_emb / EMB_D;
    int n_edges = in_sizes[1] / 2;
    int M       = in_sizes[2];
    int mtiles  = (M + BM - 1) / BM;
    int ntiles  = (n_nodes + BM - 1) / BM;

    static bool attr_done = false;
    if (!attr_done) {
        cudaFuncSetAttribute(gemm_pq,  cudaFuncAttributeMaxDynamicSharedMemorySize, SMEM_TOTAL);
        cudaFuncSetAttribute(gemm_l23, cudaFuncAttributeMaxDynamicSharedMemorySize, SMEM_TOTAL);
        attr_done = true;
    }

    prep_split<<<512, 256>>>(emb, n_emb, W1, W2);
    init_out<<<(M + 255) / 256, 256>>>(out, b3, M);
    {
        dim3 grid(PQN / BN, ntiles);     // 4 x 782
        gemm_pq<<<grid, 256, SMEM_TOTAL>>>(n_nodes);
    }
    gemm_l23<<<mtiles, 256, SMEM_TOTAL>>>(edge_index, move_idx, n_edges,
                                          b1, b2, W3, out, M);
}

// round 6
// speedup vs baseline: 6.4209x; 1.3254x over previous
#include <cuda_runtime.h>
#include <cuda_fp16.h>
#include <cstdint>

// ---------------------------------------------------------------------------
// MovePredictor: logits = W3 . relu(W2 . relu(W1.[e_src;e_tgt] + b1) + b2) + b3
//  - PQ = emb @ [W1_left; W1_right]^T over NODES (halves layer-1 FLOPs)
//  - h1[m] = relu(PQ[src,0:512] + PQ[tgt,512:1024] + b1) built on the fly
//  - fp16 2-pass GEMMs: data operand single fp16, weight operand hi+lo fp16
//  - mma.sync m16n8k16, 64x64 warp tiles, 3-stage cp.async, pass-major order
// ---------------------------------------------------------------------------

#define N_NODES_MAX 100000
#define EMB_D   256
#define H1DIM   512
#define H2DIM   256
#define PQN     1024

#define BM 128
#define BN 256
#define BK 32                    // fp16 elems per k-chunk (64B rows)
#define RS 80                    // smem row stride (64B data + 16B pad)

// stage layout (bytes): A single, B hi, B lo
#define A_O  0
#define BH_O 10240
#define BL_O 30720
#define STG  51200
#define NSTG 3
#define AUXO (STG * NSTG)        // 153600
#define SMEM_TOTAL (AUXO + 6144)

// ---- device globals (allocation-free scratch) ----
__device__ float  g_PQ[(size_t)N_NODES_MAX * PQN];     // 409.6 MB
__device__ __half g_Eh[(size_t)N_NODES_MAX * EMB_D];   // emb fp16
__device__ __half g_W1sh[(size_t)PQN * EMB_D];         // stacked W1 hi
__device__ __half g_W1sl[(size_t)PQN * EMB_D];         // stacked W1 lo
__device__ __half g_W2h[(size_t)H2DIM * H1DIM];
__device__ __half g_W2l[(size_t)H2DIM * H1DIM];

// ---------------- helpers ----------------
__device__ __forceinline__ uint32_t smem_u32(const void* p) {
    uint32_t a;
    asm("{ .reg .u64 t; cvta.to.shared.u64 t, %1; cvt.u32.u64 %0, t; }"
        : "=r"(a) : "l"(p));
    return a;
}
__device__ __forceinline__ void cp16(uint32_t dst, const void* src) {
    asm volatile("cp.async.cg.shared.global [%0], [%1], 16;" :: "r"(dst), "l"(src));
}
__device__ __forceinline__ void cp_commit() {
    asm volatile("cp.async.commit_group;" ::: "memory");
}
__device__ __forceinline__ void cp_wait0() {
    asm volatile("cp.async.wait_group 0;" ::: "memory");
}
__device__ __forceinline__ void cp_wait1() {
    asm volatile("cp.async.wait_group 1;" ::: "memory");
}
__device__ __forceinline__ void ldsm_x4(uint32_t* r, uint32_t addr) {
    asm volatile("ldmatrix.sync.aligned.m8n8.x4.shared.b16 {%0,%1,%2,%3}, [%4];"
                 : "=r"(r[0]), "=r"(r[1]), "=r"(r[2]), "=r"(r[3]) : "r"(addr));
}
__device__ __forceinline__ void mma_f16(float* c, const uint32_t* a,
                                        uint32_t b0, uint32_t b1) {
    asm volatile(
        "mma.sync.aligned.m16n8k16.row.col.f32.f16.f16.f32 "
        "{%0,%1,%2,%3}, {%4,%5,%6,%7}, {%8,%9}, {%0,%1,%2,%3};"
        : "+f"(c[0]), "+f"(c[1]), "+f"(c[2]), "+f"(c[3])
        : "r"(a[0]), "r"(a[1]), "r"(a[2]), "r"(a[3]), "r"(b0), "r"(b1));
}
__device__ __forceinline__ uint32_t pack_h2(float a, float b) {
    __half2 v(__float2half_rn(a), __float2half_rn(b));
    return *reinterpret_cast<uint32_t*>(&v);
}

// 64x64-warp MMA over one 32-k chunk; pass-major (RAW distance = 32 MMAs)
__device__ __forceinline__ void mma_chunk(uint32_t stg, int lane, int warp_m,
                                          int warp_n, float acc[4][8][4]) {
    const uint32_t aB = stg + A_O  + (warp_m * 64 + (lane & 15)) * RS + (lane >> 4) * 16;
    const uint32_t bB = stg + BH_O + (warp_n * 64 + (lane & 15)) * RS + (lane >> 4) * 16;
    #pragma unroll
    for (int kt = 0; kt < 2; kt++) {
        uint32_t aR[4][4], bH[4][4], bL[4][4];
        #pragma unroll
        for (int mt = 0; mt < 4; mt++)
            ldsm_x4(aR[mt], aB + mt * 16 * RS + kt * 32);
        #pragma unroll
        for (int nb = 0; nb < 4; nb++) {
            ldsm_x4(bH[nb], bB + nb * 16 * RS + kt * 32);
            ldsm_x4(bL[nb], bB + (BL_O - BH_O) + nb * 16 * RS + kt * 32);
        }
        #pragma unroll
        for (int mt = 0; mt < 4; mt++)
            #pragma unroll
            for (int nb = 0; nb < 4; nb++) {
                mma_f16(acc[mt][2 * nb],     aR[mt], bH[nb][0], bH[nb][2]);
                mma_f16(acc[mt][2 * nb + 1], aR[mt], bH[nb][1], bH[nb][3]);
            }
        #pragma unroll
        for (int mt = 0; mt < 4; mt++)
            #pragma unroll
            for (int nb = 0; nb < 4; nb++) {
                mma_f16(acc[mt][2 * nb],     aR[mt], bL[nb][0], bL[nb][2]);
                mma_f16(acc[mt][2 * nb + 1], aR[mt], bL[nb][1], bL[nb][3]);
            }
    }
}

// ---------------- prep: emb->fp16, stacked-W1 & W2 -> fp16 hi/lo ----------------
__global__ void prep_split(const float* __restrict__ emb, int n_emb,
                           const float* __restrict__ W1,
                           const float* __restrict__ W2)
{
    int total = n_emb + PQN * EMB_D + H2DIM * H1DIM;
    for (int i = blockIdx.x * blockDim.x + threadIdx.x; i < total;
         i += gridDim.x * blockDim.x) {
        if (i < n_emb) {
            g_Eh[i] = __float2half_rn(emb[i]);
        } else if (i < n_emb + PQN * EMB_D) {
            int j = i - n_emb;
            int r = j >> 8, k = j & 255;
            float x = W1[(size_t)(r & 511) * 512 + k + ((r >> 9) << 8)];
            __half h = __float2half_rn(x);
            g_W1sh[j] = h;
            g_W1sl[j] = __float2half_rn(x - __half2float(h));
        } else {
            int j = i - n_emb - PQN * EMB_D;
            float x = W2[j];
            __half h = __float2half_rn(x);
            g_W2h[j] = h;
            g_W2l[j] = __float2half_rn(x - __half2float(h));
        }
    }
}
__global__ void init_out(float* __restrict__ out, const float* __restrict__ b3, int M)
{
    int i = blockIdx.x * blockDim.x + threadIdx.x;
    if (i < M) out[i] = b3[0];
}

// ---------------- GEMM 1: PQ = emb @ W1s^T  (M=n_nodes, N=1024, K=256) ----------------
__global__ __launch_bounds__(256, 1)
void gemm_pq(int n_nodes)
{
    extern __shared__ char sm[];
    const uint32_t sb = smem_u32(sm);
    const int t = threadIdx.x, lane = t & 31, w = t >> 5;
    const int warp_m = w >> 2, warp_n = w & 3;
    const int m0 = blockIdx.y * BM;
    const int n0 = blockIdx.x * BN;

    float acc[4][8][4];
    #pragma unroll
    for (int a = 0; a < 4; a++)
        #pragma unroll
        for (int b = 0; b < 8; b++)
            #pragma unroll
            for (int c = 0; c < 4; c++) acc[a][b][c] = 0.f;

    auto issue = [&](int stage, int ch) {
        uint32_t sg = sb + stage * STG;
        int k0 = ch * BK;
        #pragma unroll
        for (int i = 0; i < 2; i++) {            // A: 512 cp16
            int g = t + i * 256;
            int row = g >> 2, c = g & 3;
            int gm = m0 + row; if (gm >= n_nodes) gm = n_nodes - 1;
            cp16(sg + A_O + row * RS + c * 16,
                 g_Eh + (size_t)gm * EMB_D + k0 + c * 8);
        }
        #pragma unroll
        for (int i = 0; i < 8; i++) {            // B hi+lo: 2048 cp16
            int g = t + i * 256;
            int buf = g >> 10, rem = g & 1023;
            int row = rem >> 2, c = rem & 3;
            const __half* src = (buf ? g_W1sl : g_W1sh) +
                                (size_t)(n0 + row) * EMB_D + k0 + c * 8;
            cp16(sg + (buf ? BL_O : BH_O) + row * RS + c * 16, src);
        }
        cp_commit();
    };

    const int CH = EMB_D / BK;       // 8
    issue(0, 0); issue(1, 1);
    for (int ch = 0; ch < CH; ch++) {
        if (ch + 2 < CH) cp_wait1(); else cp_wait0();
        __syncthreads();
        if (ch + 2 < CH) issue((ch + 2) % NSTG, ch + 2);
        mma_chunk(sb + (ch % NSTG) * STG, lane, warp_m, warp_n, acc);
        __syncthreads();
    }

    #pragma unroll
    for (int mt = 0; mt < 4; mt++)
        #pragma unroll
        for (int h = 0; h < 2; h++) {
            int r = m0 + warp_m * 64 + mt * 16 + (lane >> 2) + 8 * h;
            if (r < n_nodes) {
                #pragma unroll
                for (int nb = 0; nb < 8; nb++) {
                    int c = n0 + warp_n * 64 + nb * 8 + (lane & 3) * 2;
                    float2 v{acc[mt][nb][2 * h], acc[mt][nb][2 * h + 1]};
                    *(float2*)(g_PQ + (size_t)r * PQN + c) = v;
                }
            }
        }
}

// ---------------- GEMM 2+3: h1 on-the-fly, GEMM vs W2, relu, dot W3 ----------------
__global__ __launch_bounds__(256, 1)
void gemm_l23(const int* __restrict__ edge_index,
              const int* __restrict__ move_idx, int n_edges,
              const float* __restrict__ b1, const float* __restrict__ b2,
              const float* __restrict__ W3, float* __restrict__ out, int M)
{
    extern __shared__ char sm[];
    const uint32_t sb = smem_u32(sm);
    const int t = threadIdx.x, lane = t & 31, w = t >> 5;
    const int warp_m = w >> 2, warp_n = w & 3;
    const int m0 = blockIdx.x * BM;

    int*   offS = (int*)(sm + AUXO);
    int*   offT = (int*)(sm + AUXO + 512);
    float* b1s  = (float*)(sm + AUXO + 1024);     // 512 floats
    float* b2s  = (float*)(sm + AUXO + 3072);     // 256 floats
    float* w3s  = (float*)(sm + AUXO + 4096);     // 256 floats

    if (t < 128) {
        int m = m0 + t; if (m >= M) m = M - 1;
        int e = move_idx[t + m0 - m0 + (m - m0) + m0 == 0 ? move_idx[m] * 0 : 0]; // (no-op guard removed below)
        (void)e;
    }
    if (t < 128) {
        int m = m0 + t; if (m >= M) m = M - 1;
        int e = move_idx[m];
        offS[t] = edge_index[e] * PQN;
        offT[t] = edge_index[n_edges + e] * PQN + 512;
    }
    b1s[t]       = b1[t];
    b1s[t + 256] = b1[t + 256];
    if (t < 256) { b2s[t] = b2[t]; w3s[t] = W3[t]; }
    __syncthreads();

    float acc[4][8][4];
    #pragma unroll
    for (int a = 0; a < 4; a++)
        #pragma unroll
        for (int b = 0; b < 8; b++)
            #pragma unroll
            for (int c = 0; c < 4; c++) acc[a][b][c] = 0.f;

    const int r  = t >> 1;           // A row handled by this thread
    const int hh = t & 1;            // 16-col half

    auto issueB = [&](int stage, int ch) {
        uint32_t sg = sb + stage * STG;
        int k0 = ch * BK;
        #pragma unroll
        for (int i = 0; i < 8; i++) {
            int g = t + i * 256;
            int buf = g >> 10, rem = g & 1023;
            int row = rem >> 2, c = rem & 3;
            const __half* src = (buf ? g_W2l : g_W2h) +
                                (size_t)row * H1DIM + k0 + c * 8;
            cp16(sg + (buf ? BL_O : BH_O) + row * RS + c * 16, src);
        }
        cp_commit();
    };
    auto ldgA = [&](int ch, float4* S, float4* T) {
        int cb = ch * BK + hh * 16;
        const float* ps = g_PQ + offS[r] + cb;
        const float* pt = g_PQ + offT[r] + cb;
        #pragma unroll
        for (int q = 0; q < 4; q++) {
            S[q] = *(const float4*)(ps + q * 4);
            T[q] = *(const float4*)(pt + q * 4);
        }
    };
    auto stsA = [&](int stage, int ch, const float4* S, const float4* T) {
        uint32_t o = stage * STG + A_O + r * RS + hh * 32;
        int cb = ch * BK + hh * 16;
        #pragma unroll
        for (int q = 0; q < 4; q++) {
            int c = cb + q * 4;
            float u0 = S[q].x + T[q].x + b1s[c];
            float u1 = S[q].y + T[q].y + b1s[c + 1];
            float u2 = S[q].z + T[q].z + b1s[c + 2];
            float u3 = S[q].w + T[q].w + b1s[c + 3];
            u0 = u0 > 0.f ? u0 : 0.f;  u1 = u1 > 0.f ? u1 : 0.f;
            u2 = u2 > 0.f ? u2 : 0.f;  u3 = u3 > 0.f ? u3 : 0.f;
            *(uint2*)(sm + o + q * 8) = uint2{pack_h2(u0, u1), pack_h2(u2, u3)};
        }
    };

    const int CH = H1DIM / BK;       // 16
    // prologue
    issueB(0, 0); issueB(1, 1);
    {
        float4 S[4], T[4];
        ldgA(0, S, T);
        stsA(0, 0, S, T);
    }
    for (int ch = 0; ch < CH; ch++) {
        if (ch + 2 < CH) cp_wait1(); else cp_wait0();
        __syncthreads();
        if (ch + 2 < CH) issueB((ch + 2) % NSTG, ch + 2);
        float4 S[4], T[4];
        const bool more = (ch + 1 < CH);
        if (more) ldgA(ch + 1, S, T);
        mma_chunk(sb + (ch % NSTG) * STG, lane, warp_m, warp_n, acc);
        if (more) stsA((ch + 1) % NSTG, ch + 1, S, T);
    }

    // epilogue: +b2, relu, dot w3, quad-reduce, atomicAdd
    #pragma unroll
    for (int mt = 0; mt < 4; mt++)
        #pragma unroll
        for (int h = 0; h < 2; h++) {
            int rr = m0 + warp_m * 64 + mt * 16 + (lane >> 2) + 8 * h;
            float p = 0.f;
            #pragma unroll
            for (int nb = 0; nb < 8; nb++) {
                int c = warp_n * 64 + nb * 8 + (lane & 3) * 2;
                float v0 = acc[mt][nb][2 * h]     + b2s[c];
                float v1 = acc[mt][nb][2 * h + 1] + b2s[c + 1];
                v0 = v0 > 0.f ? v0 : 0.f;
                v1 = v1 > 0.f ? v1 : 0.f;
                p += v0 * w3s[c] + v1 * w3s[c + 1];
            }
            p += __shfl_xor_sync(0xffffffffu, p, 1);
            p += __shfl_xor_sync(0xffffffffu, p, 2);
            if ((lane & 3) == 0 && rr < M) atomicAdd(out + rr, p);
        }
}

// ---------------- launch ----------------
extern "C" void kernel_launch(void* const* d_in, const int* in_sizes, int n_in,
                              void* d_out, int out_size)
{
    const float* emb        = (const float*)d_in[0];
    const int*   edge_index = (const int*)d_in[1];
    const int*   move_idx   = (const int*)d_in[2];
    const float* W1 = (const float*)d_in[3];
    const float* b1 = (const float*)d_in[4];
    const float* W2 = (const float*)d_in[5];
    const float* b2 = (const float*)d_in[6];
    const float* W3 = (const float*)d_in[7];
    const float* b3 = (const float*)d_in[8];
    float* out = (float*)d_out;

    int n_emb   = in_sizes[0];
    int n_nodes = n_emb / EMB_D;
    int n_edges = in_sizes[1] / 2;
    int M       = in_sizes[2];
    int mtiles  = (M + BM - 1) / BM;
    int ntiles  = (n_nodes + BM - 1) / BM;

    cudaFuncSetAttribute(gemm_pq,  cudaFuncAttributeMaxDynamicSharedMemorySize, SMEM_TOTAL);
    cudaFuncSetAttribute(gemm_l23, cudaFuncAttributeMaxDynamicSharedMemorySize, SMEM_TOTAL);

    prep_split<<<512, 256>>>(emb, n_emb, W1, W2);
    init_out<<<(M + 255) / 256, 256>>>(out, b3, M);
    {
        dim3 grid(PQN / BN, ntiles);     // 4 x 782
        gemm_pq<<<grid, 256, SMEM_TOTAL>>>(n_nodes);
    }
    gemm_l23<<<mtiles, 256, SMEM_TOTAL>>>(edge_index, move_idx, n_edges,
                                          b1, b2, W3, out, M);
}

// round 7
// speedup vs baseline: 6.8041x; 1.0597x over previous
#include <cuda_runtime.h>
#include <cuda_fp16.h>
#include <cstdint>

// ---------------------------------------------------------------------------
// MovePredictor: logits = W3 . relu(W2 . relu(W1.[e_src;e_tgt] + b1) + b2) + b3
//  - PQ = emb @ [W1_left; W1_right]^T over NODES (halves layer-1 FLOPs);
//    b1 folded into the P half.
//  - h1[m] = relu(PQ[src,0:512] + PQ[tgt,512:1024]) built on the fly
//  - fp16 2-pass GEMMs (data fp16, weights hi+lo fp16)
//  - 512-thread CTAs, 16 warps, 64x32 warp tiles (CTA tile 128x256),
//    3-stage cp.async pipeline.
// ---------------------------------------------------------------------------

#define N_NODES_MAX 100000
#define EMB_D   256
#define H1DIM   512
#define H2DIM   256
#define PQN     1024

#define BM 128
#define BN 256
#define BK 32
#define RS 80
#define NT 512                   // threads per CTA

#define A_O  0
#define BH_O 10240
#define BL_O 30720
#define STG  51200
#define NSTG 3
#define AUXO (STG * NSTG)
#define SMEM_TOTAL (AUXO + 4096)

// ---- device globals (allocation-free scratch) ----
__device__ float  g_PQ[(size_t)N_NODES_MAX * PQN];
__device__ __half g_Eh[(size_t)N_NODES_MAX * EMB_D];
__device__ __half g_W1sh[(size_t)PQN * EMB_D];
__device__ __half g_W1sl[(size_t)PQN * EMB_D];
__device__ __half g_W2h[(size_t)H2DIM * H1DIM];
__device__ __half g_W2l[(size_t)H2DIM * H1DIM];

// ---------------- helpers ----------------
__device__ __forceinline__ uint32_t smem_u32(const void* p) {
    uint32_t a;
    asm("{ .reg .u64 t; cvta.to.shared.u64 t, %1; cvt.u32.u64 %0, t; }"
        : "=r"(a) : "l"(p));
    return a;
}
__device__ __forceinline__ void cp16(uint32_t dst, const void* src) {
    asm volatile("cp.async.cg.shared.global [%0], [%1], 16;" :: "r"(dst), "l"(src));
}
__device__ __forceinline__ void cp_commit() {
    asm volatile("cp.async.commit_group;" ::: "memory");
}
__device__ __forceinline__ void cp_wait0() {
    asm volatile("cp.async.wait_group 0;" ::: "memory");
}
__device__ __forceinline__ void cp_wait1() {
    asm volatile("cp.async.wait_group 1;" ::: "memory");
}
__device__ __forceinline__ void ldsm_x4(uint32_t* r, uint32_t addr) {
    asm volatile("ldmatrix.sync.aligned.m8n8.x4.shared.b16 {%0,%1,%2,%3}, [%4];"
                 : "=r"(r[0]), "=r"(r[1]), "=r"(r[2]), "=r"(r[3]) : "r"(addr));
}
__device__ __forceinline__ void mma_f16(float* c, const uint32_t* a,
                                        uint32_t b0, uint32_t b1) {
    asm volatile(
        "mma.sync.aligned.m16n8k16.row.col.f32.f16.f16.f32 "
        "{%0,%1,%2,%3}, {%4,%5,%6,%7}, {%8,%9}, {%0,%1,%2,%3};"
        : "+f"(c[0]), "+f"(c[1]), "+f"(c[2]), "+f"(c[3])
        : "r"(a[0]), "r"(a[1]), "r"(a[2]), "r"(a[3]), "r"(b0), "r"(b1));
}
__device__ __forceinline__ uint32_t pack_h2(float a, float b) {
    __half2 v(__float2half_rn(a), __float2half_rn(b));
    return *reinterpret_cast<uint32_t*>(&v);
}

// 64x32 warp tile over one 32-k chunk; pass-major hi then lo per kt.
__device__ __forceinline__ void mma_chunk(uint32_t stg, int lane, int warp_m,
                                          int warp_n, float acc[4][4][4]) {
    const uint32_t aB = stg + A_O  + (warp_m * 64 + (lane & 15)) * RS + (lane >> 4) * 16;
    const uint32_t bB = stg + BH_O + (warp_n * 32 + (lane & 15)) * RS + (lane >> 4) * 16;
    #pragma unroll
    for (int kt = 0; kt < 2; kt++) {
        uint32_t aR[4][4], bH[2][4], bL[2][4];
        #pragma unroll
        for (int mt = 0; mt < 4; mt++)
            ldsm_x4(aR[mt], aB + mt * 16 * RS + kt * 32);
        #pragma unroll
        for (int nb = 0; nb < 2; nb++) {
            ldsm_x4(bH[nb], bB + nb * 16 * RS + kt * 32);
            ldsm_x4(bL[nb], bB + (BL_O - BH_O) + nb * 16 * RS + kt * 32);
        }
        #pragma unroll
        for (int mt = 0; mt < 4; mt++)
            #pragma unroll
            for (int nb = 0; nb < 2; nb++) {
                mma_f16(acc[mt][2 * nb],     aR[mt], bH[nb][0], bH[nb][2]);
                mma_f16(acc[mt][2 * nb + 1], aR[mt], bH[nb][1], bH[nb][3]);
            }
        #pragma unroll
        for (int mt = 0; mt < 4; mt++)
            #pragma unroll
            for (int nb = 0; nb < 2; nb++) {
                mma_f16(acc[mt][2 * nb],     aR[mt], bL[nb][0], bL[nb][2]);
                mma_f16(acc[mt][2 * nb + 1], aR[mt], bL[nb][1], bL[nb][3]);
            }
    }
}

// ---------------- prep ----------------
__global__ void prep_split(const float* __restrict__ emb, int n_emb,
                           const float* __restrict__ W1,
                           const float* __restrict__ W2)
{
    int total = n_emb + PQN * EMB_D + H2DIM * H1DIM;
    for (int i = blockIdx.x * blockDim.x + threadIdx.x; i < total;
         i += gridDim.x * blockDim.x) {
        if (i < n_emb) {
            g_Eh[i] = __float2half_rn(emb[i]);
        } else if (i < n_emb + PQN * EMB_D) {
            int j = i - n_emb;
            int r = j >> 8, k = j & 255;
            float x = W1[(size_t)(r & 511) * 512 + k + ((r >> 9) << 8)];
            __half h = __float2half_rn(x);
            g_W1sh[j] = h;
            g_W1sl[j] = __float2half_rn(x - __half2float(h));
        } else {
            int j = i - n_emb - PQN * EMB_D;
            float x = W2[j];
            __half h = __float2half_rn(x);
            g_W2h[j] = h;
            g_W2l[j] = __float2half_rn(x - __half2float(h));
        }
    }
}
__global__ void init_out(float* __restrict__ out, const float* __restrict__ b3, int M)
{
    int i = blockIdx.x * blockDim.x + threadIdx.x;
    if (i < M) out[i] = b3[0];
}

// ---------------- GEMM 1: PQ = emb @ W1s^T (+b1 on P half) ----------------
__global__ __launch_bounds__(NT, 1)
void gemm_pq(const float* __restrict__ b1, int n_nodes)
{
    extern __shared__ char sm[];
    const uint32_t sb = smem_u32(sm);
    const int t = threadIdx.x, lane = t & 31, w = t >> 5;
    const int warp_m = w >> 3, warp_n = w & 7;
    const int m0 = blockIdx.y * BM;
    const int n0 = blockIdx.x * BN;

    float acc[4][4][4];
    #pragma unroll
    for (int a = 0; a < 4; a++)
        #pragma unroll
        for (int b = 0; b < 4; b++)
            #pragma unroll
            for (int c = 0; c < 4; c++) acc[a][b][c] = 0.f;

    auto issue = [&](int stage, int ch) {
        uint32_t sg = sb + stage * STG;
        int k0 = ch * BK;
        {   // A: 512 cp16
            int row = t >> 2, c = t & 3;
            int gm = m0 + row; if (gm >= n_nodes) gm = n_nodes - 1;
            cp16(sg + A_O + row * RS + c * 16,
                 g_Eh + (size_t)gm * EMB_D + k0 + c * 8);
        }
        #pragma unroll
        for (int i = 0; i < 4; i++) {            // B hi+lo: 2048 cp16
            int g = t + i * NT;
            int buf = g >> 10, rem = g & 1023;
            int row = rem >> 2, c = rem & 3;
            const __half* src = (buf ? g_W1sl : g_W1sh) +
                                (size_t)(n0 + row) * EMB_D + k0 + c * 8;
            cp16(sg + (buf ? BL_O : BH_O) + row * RS + c * 16, src);
        }
        cp_commit();
    };

    const int CH = EMB_D / BK;       // 8
    issue(0, 0); issue(1, 1);
    for (int ch = 0; ch < CH; ch++) {
        if (ch + 2 < CH) cp_wait1(); else cp_wait0();
        __syncthreads();
        if (ch + 2 < CH) issue((ch + 2) % NSTG, ch + 2);
        mma_chunk(sb + (ch % NSTG) * STG, lane, warp_m, warp_n, acc);
        __syncthreads();
    }

    // store fp32 PQ; fold b1 into the P half (global cols < 512)
    #pragma unroll
    for (int mt = 0; mt < 4; mt++)
        #pragma unroll
        for (int h = 0; h < 2; h++) {
            int r = m0 + warp_m * 64 + mt * 16 + (lane >> 2) + 8 * h;
            if (r < n_nodes) {
                #pragma unroll
                for (int nb = 0; nb < 4; nb++) {
                    int c = n0 + warp_n * 32 + nb * 8 + (lane & 3) * 2;
                    float v0 = acc[mt][nb][2 * h];
                    float v1 = acc[mt][nb][2 * h + 1];
                    if (c < 512) { v0 += b1[c]; v1 += b1[c + 1]; }
                    *(float2*)(g_PQ + (size_t)r * PQN + c) = float2{v0, v1};
                }
            }
        }
}

// ---------------- GEMM 2+3: h1 on-the-fly, GEMM vs W2, relu, dot W3 ----------------
__global__ __launch_bounds__(NT, 1)
void gemm_l23(const int* __restrict__ edge_index,
              const int* __restrict__ move_idx, int n_edges,
              const float* __restrict__ b2,
              const float* __restrict__ W3, float* __restrict__ out, int M)
{
    extern __shared__ char sm[];
    const uint32_t sb = smem_u32(sm);
    const int t = threadIdx.x, lane = t & 31, w = t >> 5;
    const int warp_m = w >> 3, warp_n = w & 7;
    const int m0 = blockIdx.x * BM;

    int*   offS = (int*)(sm + AUXO);
    int*   offT = (int*)(sm + AUXO + 512);
    float* b2s  = (float*)(sm + AUXO + 1024);
    float* w3s  = (float*)(sm + AUXO + 2048);

    if (t < 128) {
        int m = m0 + t; if (m >= M) m = M - 1;
        int e = move_idx[m];
        offS[t] = edge_index[e] * PQN;
        offT[t] = edge_index[n_edges + e] * PQN + 512;
    } else if (t < 384) {
        int c = t - 128;
        if (c < 256) b2s[c] = b2[c];
    } else {
        int c = t - 384;
        if (c < 256) { }
    }
    if (t >= 256 && t < 512) w3s[t - 256] = W3[t - 256];
    __syncthreads();

    float acc[4][4][4];
    #pragma unroll
    for (int a = 0; a < 4; a++)
        #pragma unroll
        for (int b = 0; b < 4; b++)
            #pragma unroll
            for (int c = 0; c < 4; c++) acc[a][b][c] = 0.f;

    const int r = t >> 2;            // A row (0..127)
    const int q = t & 3;             // 8-col group

    auto issueB = [&](int stage, int ch) {
        uint32_t sg = sb + stage * STG;
        int k0 = ch * BK;
        #pragma unroll
        for (int i = 0; i < 4; i++) {
            int g = t + i * NT;
            int buf = g >> 10, rem = g & 1023;
            int row = rem >> 2, c = rem & 3;
            const __half* src = (buf ? g_W2l : g_W2h) +
                                (size_t)row * H1DIM + k0 + c * 8;
            cp16(sg + (buf ? BL_O : BH_O) + row * RS + c * 16, src);
        }
        cp_commit();
    };
    auto ldgA = [&](int ch, float4* S, float4* T) {
        int cb = ch * BK + q * 8;
        const float* ps = g_PQ + offS[r] + cb;
        const float* pt = g_PQ + offT[r] + cb;
        S[0] = *(const float4*)(ps);
        S[1] = *(const float4*)(ps + 4);
        T[0] = *(const float4*)(pt);
        T[1] = *(const float4*)(pt + 4);
    };
    auto stsA = [&](int stage, const float4* S, const float4* T) {
        uint32_t o = stage * STG + A_O + r * RS + q * 16;
        float u0 = S[0].x + T[0].x;  float u1 = S[0].y + T[0].y;
        float u2 = S[0].z + T[0].z;  float u3 = S[0].w + T[0].w;
        float u4 = S[1].x + T[1].x;  float u5 = S[1].y + T[1].y;
        float u6 = S[1].z + T[1].z;  float u7 = S[1].w + T[1].w;
        u0 = u0 > 0.f ? u0 : 0.f;  u1 = u1 > 0.f ? u1 : 0.f;
        u2 = u2 > 0.f ? u2 : 0.f;  u3 = u3 > 0.f ? u3 : 0.f;
        u4 = u4 > 0.f ? u4 : 0.f;  u5 = u5 > 0.f ? u5 : 0.f;
        u6 = u6 > 0.f ? u6 : 0.f;  u7 = u7 > 0.f ? u7 : 0.f;
        uint4 v{pack_h2(u0, u1), pack_h2(u2, u3), pack_h2(u4, u5), pack_h2(u6, u7)};
        *(uint4*)(sm + o) = v;
    };

    const int CH = H1DIM / BK;       // 16
    issueB(0, 0); issueB(1, 1);
    {
        float4 S[2], T[2];
        ldgA(0, S, T);
        stsA(0, S, T);
    }
    for (int ch = 0; ch < CH; ch++) {
        if (ch + 2 < CH) cp_wait1(); else cp_wait0();
        __syncthreads();
        if (ch + 2 < CH) issueB((ch + 2) % NSTG, ch + 2);
        float4 S[2], T[2];
        const bool more = (ch + 1 < CH);
        if (more) ldgA(ch + 1, S, T);
        mma_chunk(sb + (ch % NSTG) * STG, lane, warp_m, warp_n, acc);
        if (more) stsA((ch + 1) % NSTG, S, T);
    }

    // epilogue: +b2, relu, dot w3, quad-reduce, atomicAdd
    #pragma unroll
    for (int mt = 0; mt < 4; mt++)
        #pragma unroll
        for (int h = 0; h < 2; h++) {
            int rr = m0 + warp_m * 64 + mt * 16 + (lane >> 2) + 8 * h;
            float p = 0.f;
            #pragma unroll
            for (int nb = 0; nb < 4; nb++) {
                int c = warp_n * 32 + nb * 8 + (lane & 3) * 2;
                float v0 = acc[mt][nb][2 * h]     + b2s[c];
                float v1 = acc[mt][nb][2 * h + 1] + b2s[c + 1];
                v0 = v0 > 0.f ? v0 : 0.f;
                v1 = v1 > 0.f ? v1 : 0.f;
                p += v0 * w3s[c] + v1 * w3s[c + 1];
            }
            p += __shfl_xor_sync(0xffffffffu, p, 1);
            p += __shfl_xor_sync(0xffffffffu, p, 2);
            if ((lane & 3) == 0 && rr < M) atomicAdd(out + rr, p);
        }
}

// ---------------- launch ----------------
extern "C" void kernel_launch(void* const* d_in, const int* in_sizes, int n_in,
                              void* d_out, int out_size)
{
    const float* emb        = (const float*)d_in[0];
    const int*   edge_index = (const int*)d_in[1];
    const int*   move_idx   = (const int*)d_in[2];
    const float* W1 = (const float*)d_in[3];
    const float* b1 = (const float*)d_in[4];
    const float* W2 = (const float*)d_in[5];
    const float* b2 = (const float*)d_in[6];
    const float* W3 = (const float*)d_in[7];
    const float* b3 = (const float*)d_in[8];
    float* out = (float*)d_out;

    int n_emb   = in_sizes[0];
    int n_nodes = n_emb / EMB_D;
    int n_edges = in_sizes[1] / 2;
    int M       = in_sizes[2];
    int mtiles  = (M + BM - 1) / BM;
    int ntiles  = (n_nodes + BM - 1) / BM;

    cudaFuncSetAttribute(gemm_pq,  cudaFuncAttributeMaxDynamicSharedMemorySize, SMEM_TOTAL);
    cudaFuncSetAttribute(gemm_l23, cudaFuncAttributeMaxDynamicSharedMemorySize, SMEM_TOTAL);

    prep_split<<<512, 256>>>(emb, n_emb, W1, W2);
    init_out<<<(M + 255) / 256, 256>>>(out, b3, M);
    {
        dim3 grid(PQN / BN, ntiles);
        gemm_pq<<<grid, NT, SMEM_TOTAL>>>(b1, n_nodes);
    }
    gemm_l23<<<mtiles, NT, SMEM_TOTAL>>>(edge_index, move_idx, n_edges,
                                         b2, W3, out, M);
}